// round 1
// baseline (speedup 1.0000x reference)
#include <cuda_runtime.h>
#include <math.h>

// Problem shape (fixed per reference): x [32, 512, 2048] f32, codebook [1024, 512] f32.
// out = gathered codebook rows laid out back as [N, C, T], plus two scalar zeros.
#define NB 32
#define CD 512
#define TD 2048
#define KC 1024
#define NT_ROWS (NB * TD)          // 65536 (n,t) rows
#define XD_ELEMS ((long long)NB * CD * TD)

// Scratch (no cudaMalloc allowed): per-row winning code index + half codebook norms.
__device__ int   g_code_idx[NT_ROWS];
__device__ float g_half_cnorm[KC];

// ---------------------------------------------------------------------------
// Kernel 1: half squared norms of each codebook row. 1024 blocks x 128 threads.
// ---------------------------------------------------------------------------
__global__ void vq_cnorm_kernel(const float* __restrict__ cb)
{
    const int k   = blockIdx.x;
    const int tid = threadIdx.x;                       // 128 threads, 4 floats each
    const float4 v = reinterpret_cast<const float4*>(cb + (size_t)k * CD)[tid];
    float s = v.x * v.x + v.y * v.y + v.z * v.z + v.w * v.w;
#pragma unroll
    for (int o = 16; o > 0; o >>= 1) s += __shfl_xor_sync(0xffffffffu, s, o);
    __shared__ float ws[4];
    if ((tid & 31) == 0) ws[tid >> 5] = s;
    __syncthreads();
    if (tid == 0) g_half_cnorm[k] = 0.5f * (ws[0] + ws[1] + ws[2] + ws[3]);
}

// ---------------------------------------------------------------------------
// Kernel 2: fused GEMM + argmax(dot - 0.5*||c||^2)  ==  argmin distance.
// Block = 128 rows (consecutive t within one n) x all 1024 codes (8 tiles of 128).
// Inner GEMM tile: 128x128x8, 256 threads, 8x8 micro-tile, smem double-buffered.
// x is [N, C, T] so a row-tile of 128 consecutive t gives perfectly coalesced
// loads of Xs[cc][tt] (the "transpose" is free).
// ---------------------------------------------------------------------------
__global__ __launch_bounds__(256) void vq_argmin_kernel(
    const float* __restrict__ x, const float* __restrict__ cb)
{
    __shared__ float Xs[2][8][128];
    __shared__ float Cs[2][8][128];
    __shared__ float s_rv[128][17];   // padded: 16-entry cross-thread reduce per row
    __shared__ int   s_ri[128][17];

    const int tid = threadIdx.x;
    const int r0  = blockIdx.x * 128;          // first (n,t) row of this block
    const int n   = r0 >> 11;                  // / 2048
    const int t0  = r0 & (TD - 1);
    const float* xbase = x + (size_t)n * CD * TD + t0;

    const int tx = tid & 15;                   // code group   (8 codes each)
    const int ty = tid >> 4;                   // row group    (8 rows each)

    // gmem staging assignments (one float4 per thread per chunk)
    const int x_cc = tid >> 5;                 // 0..7  (c within chunk)
    const int x_t4 = (tid & 31) << 2;          // 0..124 (t, x4)
    const int c_kk = tid >> 1;                 // 0..127 (code)
    const int c_c4 = (tid & 1) << 2;           // 0 or 4 (c within chunk, x4)

    float bestv[8];
    int   besti[8];
#pragma unroll
    for (int i = 0; i < 8; ++i) { bestv[i] = -INFINITY; besti[i] = 0; }

    for (int kt = 0; kt < 8; ++kt) {           // 8 code tiles of 128
        const int k0 = kt << 7;

        float acc[8][8];
#pragma unroll
        for (int i = 0; i < 8; ++i)
#pragma unroll
            for (int j = 0; j < 8; ++j) acc[i][j] = 0.0f;

        // prefetch chunk 0 of the C-dimension
        float4 xa = *reinterpret_cast<const float4*>(xbase + (size_t)x_cc * TD + x_t4);
        float4 ca = *reinterpret_cast<const float4*>(cb + (size_t)(k0 + c_kk) * CD + c_c4);
        __syncthreads();                       // previous tile's readers done
        *reinterpret_cast<float4*>(&Xs[0][x_cc][x_t4]) = xa;
        Cs[0][c_c4 + 0][c_kk] = ca.x;
        Cs[0][c_c4 + 1][c_kk] = ca.y;
        Cs[0][c_c4 + 2][c_kk] = ca.z;
        Cs[0][c_c4 + 3][c_kk] = ca.w;
        __syncthreads();

        for (int kc = 0; kc < 64; ++kc) {      // 512 / 8 chunks over C
            const int cur = kc & 1;
            if (kc < 63) {                     // prefetch next chunk into registers
                const int cb0 = (kc + 1) << 3;
                xa = *reinterpret_cast<const float4*>(
                    xbase + (size_t)(cb0 + x_cc) * TD + x_t4);
                ca = *reinterpret_cast<const float4*>(
                    cb + (size_t)(k0 + c_kk) * CD + cb0 + c_c4);
            }
#pragma unroll
            for (int cc = 0; cc < 8; ++cc) {
                float xf[8], cf[8];
                *reinterpret_cast<float4*>(&xf[0]) =
                    *reinterpret_cast<const float4*>(&Xs[cur][cc][ty * 8]);
                *reinterpret_cast<float4*>(&xf[4]) =
                    *reinterpret_cast<const float4*>(&Xs[cur][cc][ty * 8 + 4]);
                *reinterpret_cast<float4*>(&cf[0]) =
                    *reinterpret_cast<const float4*>(&Cs[cur][cc][tx * 8]);
                *reinterpret_cast<float4*>(&cf[4]) =
                    *reinterpret_cast<const float4*>(&Cs[cur][cc][tx * 8 + 4]);
#pragma unroll
                for (int i = 0; i < 8; ++i)
#pragma unroll
                    for (int j = 0; j < 8; ++j)
                        acc[i][j] = fmaf(xf[i], cf[j], acc[i][j]);
            }
            if (kc < 63) {
                const int nxt = cur ^ 1;
                *reinterpret_cast<float4*>(&Xs[nxt][x_cc][x_t4]) = xa;
                Cs[nxt][c_c4 + 0][c_kk] = ca.x;
                Cs[nxt][c_c4 + 1][c_kk] = ca.y;
                Cs[nxt][c_c4 + 2][c_kk] = ca.z;
                Cs[nxt][c_c4 + 3][c_kk] = ca.w;
                __syncthreads();
            }
        }

        // fold this code tile into the per-row running best.
        // Ascending k with strict '>' keeps the LOWEST index on ties
        // (matches jnp.argmin first-occurrence semantics).
#pragma unroll
        for (int j = 0; j < 8; ++j) {
            const int   k = k0 + tx * 8 + j;
            const float h = __ldg(&g_half_cnorm[k]);
#pragma unroll
            for (int i = 0; i < 8; ++i) {
                const float v = acc[i][j] - h;   // dot - 0.5||c||^2 ; maximize
                if (v > bestv[i]) { bestv[i] = v; besti[i] = k; }
            }
        }
    }

    // cross-thread (16-way over tx) argmax reduce per row
#pragma unroll
    for (int i = 0; i < 8; ++i) {
        s_rv[ty * 8 + i][tx] = bestv[i];
        s_ri[ty * 8 + i][tx] = besti[i];
    }
    __syncthreads();
    if (tid < 128) {
        float bv = s_rv[tid][0];
        int   bi = s_ri[tid][0];
#pragma unroll
        for (int j = 1; j < 16; ++j) {
            const float v = s_rv[tid][j];
            const int   k = s_ri[tid][j];
            if (v > bv || (v == bv && k < bi)) { bv = v; bi = k; }
        }
        g_code_idx[r0 + tid] = bi;
    }
}

// ---------------------------------------------------------------------------
// Kernel 3: gather codebook rows back into [N, C, T] layout (+ scalar zeros).
// Thread = one (n,t): stores along t are fully coalesced; codebook (2 MB) is
// L2-resident so the per-lane scattered reads stay on-chip.
// ---------------------------------------------------------------------------
__global__ void vq_gather_kernel(const float* __restrict__ cb,
                                 float* __restrict__ out, long long out_size)
{
    const int r   = blockIdx.x * 256 + threadIdx.x;   // global (n,t) row
    const int n   = r >> 11;
    const int t   = r & (TD - 1);
    const int idx = g_code_idx[r];
    const float4* crow = reinterpret_cast<const float4*>(cb + (size_t)idx * CD);
    float* obase = out + (size_t)n * CD * TD + t;
#pragma unroll 4
    for (int c4 = 0; c4 < CD / 4; ++c4) {
        const float4 v = __ldg(crow + c4);
        obase[(size_t)(c4 * 4 + 0) * TD] = v.x;
        obase[(size_t)(c4 * 4 + 1) * TD] = v.y;
        obase[(size_t)(c4 * 4 + 2) * TD] = v.z;
        obase[(size_t)(c4 * 4 + 3) * TD] = v.w;
    }
    if (r == 0) {  // commit_loss, perplexity = 0.0 (if the harness appends them)
        for (long long e = XD_ELEMS; e < out_size; ++e) out[e] = 0.0f;
    }
}

// ---------------------------------------------------------------------------
extern "C" void kernel_launch(void* const* d_in, const int* in_sizes, int n_in,
                              void* d_out, int out_size)
{
    const float* x  = (const float*)d_in[0];
    const float* cb = (const float*)d_in[1];
    // defensive: identify operands by size (x has 33.5M elems, codebook 0.5M)
    if (n_in >= 2 && in_sizes[0] < in_sizes[1]) {
        const float* tmp = x; x = cb; cb = tmp;
    }
    float* out = (float*)d_out;

    vq_cnorm_kernel<<<KC, 128>>>(cb);
    vq_argmin_kernel<<<NT_ROWS / 128, 256>>>(x, cb);
    vq_gather_kernel<<<NT_ROWS / 256, 256>>>(cb, out, (long long)out_size);
}